// round 13
// baseline (speedup 1.0000x reference)
#include <cuda_runtime.h>
#include <cuda_bf16.h>
#include <cstdint>

#define N_NODES 400000
#define N_EDGES 1600000
#define HDIM 100
#define HDIM3 300
#define ADIM 50
#define CDIM 30
#define GTB 320          // threads for scalar tiled GEMM kernels
#define MTILE 128        // rows per CTA (400000 = 128 * 3125 exactly)
#define SXS 132          // k-major tile row stride

// ---- mma.sync gi GEMM geometry ----
#define BW 17472                 // 56*312 words per B split
#define AW 7680                  // 128*60 words per A split
#define A_OFF (2*BW)             // A base word offset in smem
#define GI_SMEM ((2*BW + 2*AW) * 4)   // 201216 bytes

typedef unsigned long long u64;

// ---------------- scratch (device globals) -------------------------------------
__device__ __align__(16) float g_h  [N_NODES * HDIM];
__device__ __align__(16) float g_h2 [N_NODES * HDIM];
__device__ __align__(16) float g_m  [N_NODES * HDIM];
__device__ __align__(16) float g_msg[N_NODES * HDIM];
__device__ __align__(16) float g_gi [(size_t)N_NODES * HDIM3];
__device__ __align__(16) uint32_t g_wbia[2][2 * BW];   // fwd/bwd wih bf16-split images
__device__ int g_row[N_EDGES];
__device__ int g_col[N_EDGES];
__device__ int g_is64;
__device__ int g_degF[N_NODES];
__device__ int g_degB[N_NODES];
__device__ int g_rptrF[N_NODES + 1];
__device__ int g_rptrB[N_NODES + 1];
__device__ int g_curF[N_NODES];
__device__ int g_curB[N_NODES];
__device__ int g_csrF[N_EDGES];
__device__ int g_csrB[N_EDGES];
__device__ int g_incl[N_NODES];
__device__ int g_bsums[512];

// ---------------- helpers --------------------------------------------------------
__device__ __forceinline__ u64 pack2(float x, float y) {
    u64 r; asm("mov.b64 %0, {%1, %2};" : "=l"(r) : "f"(x), "f"(y)); return r;
}
__device__ __forceinline__ float2 unpack2(u64 v) {
    float2 r; asm("mov.b64 {%0, %1}, %2;" : "=f"(r.x), "=f"(r.y) : "l"(v)); return r;
}
__device__ __forceinline__ void fma2(u64& d, u64 a, u64 b) {
    asm("fma.rn.f32x2 %0, %1, %2, %0;" : "+l"(d) : "l"(a), "l"(b));
}
__device__ __forceinline__ float ex2a(float x) {
    float r; asm("ex2.approx.f32 %0, %1;" : "=f"(r) : "f"(x)); return r;
}
__device__ __forceinline__ float rcpa(float x) {
    float r; asm("rcp.approx.f32 %0, %1;" : "=f"(r) : "f"(x)); return r;
}
__device__ __forceinline__ float fsigmoid(float x) {
    return rcpa(1.0f + ex2a(-1.4426950408889634f * x));
}
__device__ __forceinline__ float ftanh_(float x) {
    float e = ex2a(2.8853900817779268f * x);
    return fmaf(-2.0f, rcpa(e + 1.0f), 1.0f);
}
__device__ __forceinline__ unsigned short bfu(float x) {
    __nv_bfloat16 b = __float2bfloat16(x);
    return *reinterpret_cast<unsigned short*>(&b);
}
__device__ __forceinline__ float bff(float x) {
    return __bfloat162float(__float2bfloat16(x));
}
__device__ __forceinline__ void mma_bf16(float c[4],
    uint32_t a0, uint32_t a1, uint32_t a2, uint32_t a3,
    uint32_t b0, uint32_t b1) {
    asm volatile(
        "mma.sync.aligned.m16n8k16.row.col.f32.bf16.bf16.f32 "
        "{%0,%1,%2,%3}, {%4,%5,%6,%7}, {%8,%9}, {%0,%1,%2,%3};"
        : "+f"(c[0]), "+f"(c[1]), "+f"(c[2]), "+f"(c[3])
        : "r"(a0), "r"(a1), "r"(a2), "r"(a3), "r"(b0), "r"(b1));
}

// ---------------- edge dtype detection & normalization -------------------------
__global__ void detect_kernel(const unsigned int* __restrict__ w) {
    unsigned int v = w[2 * threadIdx.x + 1];
    unsigned int any = __ballot_sync(0xffffffffu, v != 0u);
    if (threadIdx.x == 0) g_is64 = (any == 0u) ? 1 : 0;
}

__global__ void convert_kernel(const void* __restrict__ rp, const void* __restrict__ cp,
                               int* __restrict__ ro, int* __restrict__ co) {
    int e = blockIdx.x * blockDim.x + threadIdx.x;
    if (e >= N_EDGES) return;
    if (g_is64) {
        ro[e] = (int)((const long long*)rp)[e];
        co[e] = (int)((const long long*)cp)[e];
    } else {
        ro[e] = ((const int*)rp)[e];
        co[e] = ((const int*)cp)[e];
    }
}

// ---------------- CSR build ------------------------------------------------------
__global__ void deg_kernel(const int* __restrict__ row, const int* __restrict__ col,
                           int* __restrict__ degF, int* __restrict__ degB) {
    int e = blockIdx.x * blockDim.x + threadIdx.x;
    if (e >= N_EDGES) return;
    atomicAdd(&degF[row[e]], 1);
    atomicAdd(&degB[col[e]], 1);
}

__global__ void scan_block(const int* __restrict__ deg, int* __restrict__ incl,
                           int* __restrict__ bsums, int n) {
    __shared__ int s[1024];
    int i = blockIdx.x * 1024 + threadIdx.x;
    int v = (i < n) ? deg[i] : 0;
    s[threadIdx.x] = v;
    __syncthreads();
    #pragma unroll
    for (int off = 1; off < 1024; off <<= 1) {
        int t = (threadIdx.x >= off) ? s[threadIdx.x - off] : 0;
        __syncthreads();
        s[threadIdx.x] += t;
        __syncthreads();
    }
    if (i < n) incl[i] = s[threadIdx.x];
    if (threadIdx.x == 1023) bsums[blockIdx.x] = s[1023];
}

__global__ void scan_sums(int* __restrict__ bsums, int nb) {
    if (threadIdx.x == 0) {
        int acc = 0;
        for (int b = 0; b < nb; b++) { int t = bsums[b]; bsums[b] = acc; acc += t; }
    }
}

__global__ void scan_final(const int* __restrict__ incl, const int* __restrict__ deg,
                           const int* __restrict__ bsums, int* __restrict__ rptr, int n) {
    int i = blockIdx.x * 256 + threadIdx.x;
    if (i < n) rptr[i] = incl[i] - deg[i] + bsums[i >> 10];
    if (i == n) rptr[n] = N_EDGES;
}

__global__ void scatter_kernel(const int* __restrict__ row, const int* __restrict__ col,
                               int* __restrict__ curF, int* __restrict__ curB,
                               int* __restrict__ csrF, int* __restrict__ csrB) {
    int e = blockIdx.x * blockDim.x + threadIdx.x;
    if (e >= N_EDGES) return;
    int r = row[e], c = col[e];
    int pF = atomicAdd(&curF[r], 1);
    csrF[pF] = c;
    int pB = atomicAdd(&curB[c], 1);
    csrB[pB] = r;
}

// ---------------- weight prep: Wih[100][300] -> 2 bf16-split pair images --------
__global__ void prep_wb(const float* __restrict__ W, uint32_t* __restrict__ o) {
    int e = blockIdx.x * 256 + threadIdx.x;
    if (e >= BW) return;
    int kq = e / 312, n = e - kq * 312;
    int k0 = 2 * kq, k1 = k0 + 1;
    float w0 = (k0 < 100 && n < 300) ? W[k0 * 300 + n] : 0.0f;
    float w1 = (k1 < 100 && n < 300) ? W[k1 * 300 + n] : 0.0f;
    o[e] = (uint32_t)bfu(w0) | ((uint32_t)bfu(w1) << 16);
    float r0 = w0 - bff(w0), r1 = w1 - bff(w1);
    o[BW + e] = (uint32_t)bfu(r0) | ((uint32_t)bfu(r1) << 16);
}

// ---------------- h0_T[d][n] = (features @ init_w + init_b)^T ------------------
__global__ void initT_kernel(const float* __restrict__ f, const float* __restrict__ w,
                             const float* __restrict__ b, float* __restrict__ hT) {
    __shared__ float sw[4 * HDIM];
    __shared__ float sb[HDIM];
    for (int i = threadIdx.x; i < 4 * HDIM; i += blockDim.x) sw[i] = w[i];
    for (int i = threadIdx.x; i < HDIM; i += blockDim.x) sb[i] = b[i];
    __syncthreads();
    int n = blockIdx.x * blockDim.x + threadIdx.x;
    float4 fv = *(const float4*)(f + (size_t)n * 4);
    #pragma unroll 4
    for (int d = 0; d < HDIM; d++) {
        float v = sb[d] + fv.x * sw[d] + fv.y * sw[HDIM + d]
                        + fv.z * sw[2 * HDIM + d] + fv.w * sw[3 * HDIM + d];
        hT[(size_t)d * N_NODES + n] = v;
    }
}

// ---------------- scalar tiled MLP (layer1 packed f32x2) ------------------------
__global__ void __launch_bounds__(GTB, 2) mlp_tiled(
    const float* __restrict__ HT,
    const float* __restrict__ w1, const float* __restrict__ b1,
    const float* __restrict__ w2, const float* __restrict__ b2,
    float* __restrict__ Mout) {
    extern __shared__ float sm[];
    float* sxT = sm;
    float* sw1 = sm + HDIM * SXS;
    float* sw2 = sw1 + 5000;
    float* sb  = sw2 + 5000;
    int base = blockIdx.x * MTILE;
    int lane = threadIdx.x & 31, wid = threadIdx.x >> 5;

    for (int i = threadIdx.x; i < 5000; i += GTB) { sw1[i] = w1[i]; sw2[i] = w2[i]; }
    if (threadIdx.x < 50) sb[threadIdx.x] = b1[threadIdx.x];
    else if (threadIdx.x < 150) sb[threadIdx.x] = b2[threadIdx.x - 50];
    for (int idx = threadIdx.x; idx < HDIM * 32; idx += GTB) {
        int k = idx >> 5, rq = idx & 31;
        *(float4*)(sxT + k * SXS + rq * 4) =
            *(const float4*)(HT + (size_t)k * N_NODES + base + rq * 4);
    }
    __syncthreads();

    u64 a01[5], a23[5];
    #pragma unroll
    for (int j = 0; j < 5; j++) {
        float b = sb[wid * 5 + j];
        u64 bb = pack2(b, b);
        a01[j] = bb; a23[j] = bb;
    }
    const float* xp = sxT + lane * 4;
    for (int k = 0; k < HDIM; k++) {
        float4 a = *(const float4*)(xp + k * SXS);
        u64 axy = pack2(a.x, a.y), azw = pack2(a.z, a.w);
        const float* wr = sw1 + k * ADIM + wid * 5;
        #pragma unroll
        for (int j = 0; j < 5; j++) {
            float wv = wr[j];
            u64 w2 = pack2(wv, wv);
            fma2(a01[j], axy, w2);
            fma2(a23[j], azw, w2);
        }
    }
    __syncthreads();
    #pragma unroll
    for (int j = 0; j < 5; j++) {
        float2 v01 = unpack2(a01[j]);
        float2 v23 = unpack2(a23[j]);
        float* dst = sxT + (wid * 5 + j) * SXS + lane * 4;
        dst[0] = fmaxf(v01.x, 0.0f);
        dst[1] = fmaxf(v01.y, 0.0f);
        dst[2] = fmaxf(v23.x, 0.0f);
        dst[3] = fmaxf(v23.y, 0.0f);
    }
    __syncthreads();

    u64 acc[20];
    const u64* bb = (const u64*)(sb + 50 + wid * 10);
    #pragma unroll
    for (int r = 0; r < 4; r++)
        #pragma unroll
        for (int j = 0; j < 5; j++) acc[r * 5 + j] = bb[j];
    for (int k = 0; k < ADIM; k++) {
        float4 a = *(const float4*)(xp + k * SXS);
        u64 a0 = pack2(a.x, a.x), a1p = pack2(a.y, a.y);
        u64 a2 = pack2(a.z, a.z), a3 = pack2(a.w, a.w);
        const float* wr = sw2 + k * HDIM + wid * 10;
        #pragma unroll
        for (int j = 0; j < 5; j++) {
            u64 wv = *(const u64*)(wr + 2 * j);
            fma2(acc[j],      a0,  wv);
            fma2(acc[5 + j],  a1p, wv);
            fma2(acc[10 + j], a2,  wv);
            fma2(acc[15 + j], a3,  wv);
        }
    }
    __syncthreads();
    #pragma unroll
    for (int j = 0; j < 5; j++) {
        int c = wid * 10 + 2 * j;
        #pragma unroll
        for (int r = 0; r < 4; r++) {
            float2 v = unpack2(acc[r * 5 + j]);
            sxT[c * SXS + lane * 4 + r]       = v.x;
            sxT[(c + 1) * SXS + lane * 4 + r] = v.y;
        }
    }
    __syncthreads();
    for (int idx = threadIdx.x; idx < 25 * MTILE; idx += GTB) {
        int row = idx & 127, c4 = (idx >> 7) * 4;
        float4 v = make_float4(sxT[c4 * SXS + row], sxT[(c4 + 1) * SXS + row],
                               sxT[(c4 + 2) * SXS + row], sxT[(c4 + 3) * SXS + row]);
        *(float4*)(Mout + (size_t)(base + row) * HDIM + c4) = v;
    }
}

// ---------------- warp-per-node CSR gather (index prefetch + 2x unroll) ----------
__global__ void __launch_bounds__(256) spmm_gather(
    const int* __restrict__ rptr, const int* __restrict__ csr,
    const float* __restrict__ m, float* __restrict__ msg) {
    int warp = (blockIdx.x * blockDim.x + threadIdx.x) >> 5;
    int lane = threadIdx.x & 31;
    if (warp >= N_NODES) return;
    int p0 = rptr[warp], p1 = rptr[warp + 1];
    int deg = p1 - p0;
    int pre = (lane < deg) ? csr[p0 + lane] : 0;
    float4 acc0 = make_float4(0.f, 0.f, 0.f, 0.f);
    float4 acc1 = make_float4(0.f, 0.f, 0.f, 0.f);
    int nd = min(deg, 32);
    int j = 0;
    for (; j + 1 < nd; j += 2) {
        int s0 = __shfl_sync(0xffffffffu, pre, j);
        int s1 = __shfl_sync(0xffffffffu, pre, j + 1);
        if (lane < 25) {
            float4 v0 = *(const float4*)(m + (size_t)s0 * HDIM + lane * 4);
            float4 v1 = *(const float4*)(m + (size_t)s1 * HDIM + lane * 4);
            acc0.x += v0.x; acc0.y += v0.y; acc0.z += v0.z; acc0.w += v0.w;
            acc1.x += v1.x; acc1.y += v1.y; acc1.z += v1.z; acc1.w += v1.w;
        }
    }
    if (j < nd) {
        int s0 = __shfl_sync(0xffffffffu, pre, j);
        if (lane < 25) {
            float4 v0 = *(const float4*)(m + (size_t)s0 * HDIM + lane * 4);
            acc0.x += v0.x; acc0.y += v0.y; acc0.z += v0.z; acc0.w += v0.w;
        }
    }
    for (int p = p0 + 32; p < p1; p++) {
        int s = csr[p];
        if (lane < 25) {
            float4 v = *(const float4*)(m + (size_t)s * HDIM + lane * 4);
            acc0.x += v.x; acc0.y += v.y; acc0.z += v.z; acc0.w += v.w;
        }
    }
    if (lane < 25) {
        acc0.x += acc1.x; acc0.y += acc1.y; acc0.z += acc1.z; acc0.w += acc1.w;
        *(float4*)(msg + (size_t)warp * HDIM + lane * 4) = acc0;
    }
}

// ---------------- gi via mma.sync: giT = (msg @ Wih + bih)^T --------------------
template<int NT0, int NT>
__device__ __forceinline__ void gi_compute_half(
    const uint32_t* __restrict__ smu, float* __restrict__ outT,
    const float* __restrict__ Bih, int base, int w, int lane) {
    int q = lane & 3, l4 = lane >> 2;
    int r = w * 16 + l4;
    const uint32_t* A0 = smu + A_OFF + r * 60;
    float c[NT][4];
    #pragma unroll
    for (int t = 0; t < NT; t++) { c[t][0] = c[t][1] = c[t][2] = c[t][3] = 0.0f; }
    #pragma unroll
    for (int ks = 0; ks < 7; ks++) {
        uint32_t a00 = A0[ks * 8 + q],            a01 = A0[480 + ks * 8 + q];
        uint32_t a02 = A0[ks * 8 + 4 + q],        a03 = A0[480 + ks * 8 + 4 + q];
        uint32_t a10 = A0[AW + ks * 8 + q],       a11 = A0[AW + 480 + ks * 8 + q];
        uint32_t a12 = A0[AW + ks * 8 + 4 + q],   a13 = A0[AW + 480 + ks * 8 + 4 + q];
        const uint32_t* B0 = smu + (ks * 8 + q) * 312;
        const uint32_t* B1 = smu + (ks * 8 + 4 + q) * 312;
        #pragma unroll
        for (int t = 0; t < NT; t++) {
            int nb = (NT0 + t) * 8 + l4;
            uint32_t b00 = B0[nb],       b01 = B1[nb];
            uint32_t b10 = B0[BW + nb],  b11 = B1[BW + nb];
            mma_bf16(c[t], a00, a01, a02, a03, b00, b01);
            mma_bf16(c[t], a10, a11, a12, a13, b00, b01);
            mma_bf16(c[t], a00, a01, a02, a03, b10, b11);
        }
    }
    int node = base + r;
    #pragma unroll
    for (int t = 0; t < NT; t++) {
        int n0 = (NT0 + t) * 8 + q * 2;
        if (n0 < 300) {
            float bia = Bih[n0];
            outT[(size_t)n0 * N_NODES + node]     = c[t][0] + bia;
            outT[(size_t)n0 * N_NODES + node + 8] = c[t][2] + bia;
        }
        if (n0 + 1 < 300) {
            float bib = Bih[n0 + 1];
            outT[(size_t)(n0 + 1) * N_NODES + node]     = c[t][1] + bib;
            outT[(size_t)(n0 + 1) * N_NODES + node + 8] = c[t][3] + bib;
        }
    }
}

__global__ void __launch_bounds__(256, 1) gi_mma(
    const float* __restrict__ MSG, const uint32_t* __restrict__ GB,
    const float* __restrict__ Bih, float* __restrict__ outT) {
    extern __shared__ __align__(16) uint32_t smu[];
    int tid = threadIdx.x;
    int base = blockIdx.x * MTILE;
    {
        const uint4* src = (const uint4*)GB;
        uint4* dst = (uint4*)smu;
        for (int i = tid; i < (2 * BW) / 4; i += 256) dst[i] = src[i];
    }
    for (int idx = tid; idx < 128 * 56; idx += 256) {
        int row = idx / 56;
        int kq = idx - row * 56;
        float2 v = make_float2(0.0f, 0.0f);
        if (kq < 50) v = *(const float2*)(MSG + (size_t)(base + row) * HDIM + 2 * kq);
        uint32_t hi = (uint32_t)bfu(v.x) | ((uint32_t)bfu(v.y) << 16);
        float rx = v.x - bff(v.x), ry = v.y - bff(v.y);
        uint32_t lo = (uint32_t)bfu(rx) | ((uint32_t)bfu(ry) << 16);
        smu[A_OFF + row * 60 + kq]      = hi;
        smu[A_OFF + AW + row * 60 + kq] = lo;
    }
    __syncthreads();
    int w = tid >> 5, lane = tid & 31;
    gi_compute_half<0, 19>(smu, outT, Bih, base, w, lane);
    gi_compute_half<19, 20>(smu, outT, Bih, base, w, lane);
}

// ---------------- tiled gate: wide chunks (NP col-pairs per warp) ---------------
template<int NP>
__device__ __forceinline__ void gate_chunk(
    const float* __restrict__ sxT, const float* __restrict__ sw,
    const float* __restrict__ sb,
    const float* __restrict__ GIT, float* __restrict__ HoutT,
    int d0, int base, int lane, int wid) {
    const int CPW = 2 * NP;
    const int NC = 10 * CPW;
    int cl = wid * CPW;
    const float* xp = sxT + lane * 4;
    size_t rowoff = (size_t)base + lane * 4;

    u64 ar[NP][4], az[NP][4], an[NP][4];
    #pragma unroll
    for (int p = 0; p < NP; p++) {
        u64 br = *(const u64*)(sb + d0 + cl + 2 * p);
        u64 bz = *(const u64*)(sb + HDIM + d0 + cl + 2 * p);
        u64 bn = *(const u64*)(sb + 2 * HDIM + d0 + cl + 2 * p);
        #pragma unroll
        for (int r = 0; r < 4; r++) { ar[p][r] = br; az[p][r] = bz; an[p][r] = bn; }
    }
    for (int k = 0; k < HDIM; k++) {
        float4 a = *(const float4*)(xp + k * SXS);
        u64 a0 = pack2(a.x, a.x), a1p = pack2(a.y, a.y);
        u64 a2 = pack2(a.z, a.z), a3 = pack2(a.w, a.w);
        const float* wk = sw + k * 3 * NC + cl;
        #pragma unroll
        for (int p = 0; p < NP; p++) {
            u64 wr = *(const u64*)(wk + 2 * p);
            u64 wz = *(const u64*)(wk + NC + 2 * p);
            u64 wn = *(const u64*)(wk + 2 * NC + 2 * p);
            fma2(ar[p][0], a0, wr); fma2(ar[p][1], a1p, wr);
            fma2(ar[p][2], a2, wr); fma2(ar[p][3], a3, wr);
            fma2(az[p][0], a0, wz); fma2(az[p][1], a1p, wz);
            fma2(az[p][2], a2, wz); fma2(az[p][3], a3, wz);
            fma2(an[p][0], a0, wn); fma2(an[p][1], a1p, wn);
            fma2(an[p][2], a2, wn); fma2(an[p][3], a3, wn);
        }
    }
    #pragma unroll
    for (int p = 0; p < NP; p++) {
        int c = d0 + cl + 2 * p;
        float4 gr0 = *(const float4*)(GIT + (size_t)c * N_NODES + rowoff);
        float4 gr1 = *(const float4*)(GIT + (size_t)(c + 1) * N_NODES + rowoff);
        float4 gz0 = *(const float4*)(GIT + (size_t)(HDIM + c) * N_NODES + rowoff);
        float4 gz1 = *(const float4*)(GIT + (size_t)(HDIM + c + 1) * N_NODES + rowoff);
        float4 gn0 = *(const float4*)(GIT + (size_t)(2 * HDIM + c) * N_NODES + rowoff);
        float4 gn1 = *(const float4*)(GIT + (size_t)(2 * HDIM + c + 1) * N_NODES + rowoff);
        float4 h0 = *(const float4*)(sxT + c * SXS + lane * 4);
        float4 h1 = *(const float4*)(sxT + (c + 1) * SXS + lane * 4);
        float4 o0, o1;
        const float* grp0 = &gr0.x; const float* grp1 = &gr1.x;
        const float* gzp0 = &gz0.x; const float* gzp1 = &gz1.x;
        const float* gnp0 = &gn0.x; const float* gnp1 = &gn1.x;
        const float* hp0 = &h0.x;  const float* hp1 = &h1.x;
        float* op0 = &o0.x; float* op1 = &o1.x;
        #pragma unroll
        for (int r = 0; r < 4; r++) {
            float2 hr = unpack2(ar[p][r]);
            float2 hz = unpack2(az[p][r]);
            float2 hn = unpack2(an[p][r]);
            float r0 = fsigmoid(grp0[r] + hr.x);
            float r1 = fsigmoid(grp1[r] + hr.y);
            float z0 = fsigmoid(gzp0[r] + hz.x);
            float z1 = fsigmoid(gzp1[r] + hz.y);
            float n0 = ftanh_(gnp0[r] + r0 * hn.x);
            float n1 = ftanh_(gnp1[r] + r1 * hn.y);
            op0[r] = (1.0f - z0) * n0 + z0 * hp0[r];
            op1[r] = (1.0f - z1) * n1 + z1 * hp1[r];
        }
        *(float4*)(HoutT + (size_t)c * N_NODES + rowoff) = o0;
        *(float4*)(HoutT + (size_t)(c + 1) * N_NODES + rowoff) = o1;
    }
}

// stage W strip [d0, d0+NC) of all 3 gates: sw[k*3NC + g*NC + j] = W[k*300 + g*100 + d0 + j]
template<int NC>
__device__ __forceinline__ void gate_stageW(
    float* __restrict__ sw, const float* __restrict__ W, int d0) {
    for (int i = threadIdx.x * 4; i < 300 * NC; i += GTB * 4) {
        int k = i / (3 * NC), rem = i - k * (3 * NC);
        int g = rem / NC, j = rem - g * NC;
        *(float4*)(sw + i) = *(const float4*)(W + (size_t)k * HDIM3 + g * HDIM + d0 + j);
    }
}

__global__ void __launch_bounds__(GTB, 2) gate_tiled(
    const float* __restrict__ GIT,
    const float* __restrict__ HT,
    const float* __restrict__ W, const float* __restrict__ B,
    float* __restrict__ HoutT) {
    extern __shared__ float sm[];
    float* sxT = sm;                  // 100 x 132
    float* sw  = sm + HDIM * SXS;     // up to 100 x 120
    float* sb  = sw + 12000;          // 300
    int base = blockIdx.x * MTILE;
    int lane = threadIdx.x & 31, wid = threadIdx.x >> 5;
    for (int i = threadIdx.x; i < HDIM3; i += GTB) sb[i] = B[i];
    for (int idx = threadIdx.x; idx < HDIM * 32; idx += GTB) {
        int k = idx >> 5, rq = idx & 31;
        *(float4*)(sxT + k * SXS + rq * 4) =
            *(const float4*)(HT + (size_t)k * N_NODES + base + rq * 4);
    }
    // chunk 0: cols 0..39
    __syncthreads();
    gate_stageW<40>(sw, W, 0);
    __syncthreads();
    gate_chunk<2>(sxT, sw, sb, GIT, HoutT, 0, base, lane, wid);
    // chunk 1: cols 40..79
    __syncthreads();
    gate_stageW<40>(sw, W, 40);
    __syncthreads();
    gate_chunk<2>(sxT, sw, sb, GIT, HoutT, 40, base, lane, wid);
    // chunk 2: cols 80..99
    __syncthreads();
    gate_stageW<20>(sw, W, 80);
    __syncthreads();
    gate_chunk<1>(sxT, sw, sb, GIT, HoutT, 80, base, lane, wid);
}

// ---------------- classifier from transposed h ----------------------------------
__global__ void __launch_bounds__(256) classify_kernel(
    const float* __restrict__ HT,
    const float* __restrict__ w1, const float* __restrict__ b1,
    const float* __restrict__ w2, const float* __restrict__ b2,
    float* __restrict__ out) {
    __shared__ float s1[HDIM * CDIM];
    __shared__ float sb1[CDIM];
    __shared__ float s2[CDIM];
    __shared__ float sb2;
    for (int i = threadIdx.x; i < HDIM * CDIM; i += blockDim.x) s1[i] = w1[i];
    for (int i = threadIdx.x; i < CDIM; i += blockDim.x) { sb1[i] = b1[i]; s2[i] = w2[i]; }
    if (threadIdx.x == 0) sb2 = b2[0];
    __syncthreads();
    int n = blockIdx.x * blockDim.x + threadIdx.x;
    if (n >= N_NODES) return;
    float a[CDIM];
    #pragma unroll
    for (int j = 0; j < CDIM; j++) a[j] = sb1[j];
    for (int k = 0; k < HDIM; k++) {
        float xv = HT[(size_t)k * N_NODES + n];
        const float* wr = s1 + k * CDIM;
        #pragma unroll
        for (int j = 0; j < CDIM; j++) a[j] = fmaf(xv, wr[j], a[j]);
    }
    float r = sb2;
    #pragma unroll
    for (int j = 0; j < CDIM; j++) r = fmaf(fmaxf(a[j], 0.0f), s2[j], r);
    out[n] = r;
}

// ---------------- host orchestration --------------------------------------------
extern "C" void kernel_launch(void* const* d_in, const int* in_sizes, int n_in,
                              void* d_out, int out_size) {
    const float* features = (const float*)d_in[0];
    const void*  e_row    = d_in[1];
    const void*  e_col    = d_in[2];
    const float* init_w   = (const float*)d_in[3];
    const float* init_b   = (const float*)d_in[4];
    const float* fm_w1 = (const float*)d_in[5],  *fm_b1 = (const float*)d_in[6];
    const float* fm_w2 = (const float*)d_in[7],  *fm_b2 = (const float*)d_in[8];
    const float* bm_w1 = (const float*)d_in[9],  *bm_b1 = (const float*)d_in[10];
    const float* bm_w2 = (const float*)d_in[11], *bm_b2 = (const float*)d_in[12];
    const float* fg_wih = (const float*)d_in[13], *fg_whh = (const float*)d_in[14];
    const float* fg_bih = (const float*)d_in[15], *fg_bhh = (const float*)d_in[16];
    const float* bg_wih = (const float*)d_in[17], *bg_whh = (const float*)d_in[18];
    const float* bg_bih = (const float*)d_in[19], *bg_bhh = (const float*)d_in[20];
    const float* cl_w1 = (const float*)d_in[21], *cl_b1 = (const float*)d_in[22];
    const float* cl_w2 = (const float*)d_in[23], *cl_b2 = (const float*)d_in[24];
    float* out = (float*)d_out;

    float *h, *h2, *m, *msg, *gi;
    int *row_i, *col_i, *degF, *degB, *rptrF, *rptrB, *curF, *curB, *csrF, *csrB, *incl, *bsums;
    uint32_t* wbia;
    cudaGetSymbolAddress((void**)&h,     g_h);
    cudaGetSymbolAddress((void**)&h2,    g_h2);
    cudaGetSymbolAddress((void**)&m,     g_m);
    cudaGetSymbolAddress((void**)&msg,   g_msg);
    cudaGetSymbolAddress((void**)&gi,    g_gi);
    cudaGetSymbolAddress((void**)&wbia,  g_wbia);
    cudaGetSymbolAddress((void**)&row_i, g_row);
    cudaGetSymbolAddress((void**)&col_i, g_col);
    cudaGetSymbolAddress((void**)&degF,  g_degF);
    cudaGetSymbolAddress((void**)&degB,  g_degB);
    cudaGetSymbolAddress((void**)&rptrF, g_rptrF);
    cudaGetSymbolAddress((void**)&rptrB, g_rptrB);
    cudaGetSymbolAddress((void**)&curF,  g_curF);
    cudaGetSymbolAddress((void**)&curB,  g_curB);
    cudaGetSymbolAddress((void**)&csrF,  g_csrF);
    cudaGetSymbolAddress((void**)&csrB,  g_csrB);
    cudaGetSymbolAddress((void**)&incl,  g_incl);
    cudaGetSymbolAddress((void**)&bsums, g_bsums);

    uint32_t* wbia_f = wbia;
    uint32_t* wbia_b = wbia + 2 * BW;

    const size_t smem_mlp  = (size_t)(HDIM * SXS + 5000 + 5000 + 150) * sizeof(float);
    const size_t smem_gate = (size_t)(HDIM * SXS + 12000 + 300) * sizeof(float);   // 102,000
    cudaFuncSetAttribute(mlp_tiled,  cudaFuncAttributeMaxDynamicSharedMemorySize, (int)smem_mlp);
    cudaFuncSetAttribute(gate_tiled, cudaFuncAttributeMaxDynamicSharedMemorySize, (int)smem_gate);
    cudaFuncSetAttribute(gi_mma,     cudaFuncAttributeMaxDynamicSharedMemorySize, GI_SMEM);

    const int GT    = N_NODES / MTILE;   // 3125
    const int GN256 = (N_NODES + 255) / 256;
    const int GE    = (N_EDGES + 255) / 256;
    const int GW    = (int)(((long long)N_NODES * 32 + 255) / 256);
    const int NB    = (N_NODES + 1023) / 1024;
    const int GP    = (BW + 255) / 256;

    // ---- preprocessing ----
    detect_kernel<<<1, 32>>>((const unsigned int*)e_row);
    convert_kernel<<<GE, 256>>>(e_row, e_col, row_i, col_i);
    cudaMemsetAsync(degF, 0, N_NODES * sizeof(int));
    cudaMemsetAsync(degB, 0, N_NODES * sizeof(int));
    deg_kernel<<<GE, 256>>>(row_i, col_i, degF, degB);
    scan_block<<<NB, 1024>>>(degF, incl, bsums, N_NODES);
    scan_sums<<<1, 32>>>(bsums, NB);
    scan_final<<<(N_NODES + 256) / 256, 256>>>(incl, degF, bsums, rptrF, N_NODES);
    scan_block<<<NB, 1024>>>(degB, incl, bsums, N_NODES);
    scan_sums<<<1, 32>>>(bsums, NB);
    scan_final<<<(N_NODES + 256) / 256, 256>>>(incl, degB, bsums, rptrB, N_NODES);
    cudaMemcpyAsync(curF, rptrF, N_NODES * sizeof(int), cudaMemcpyDeviceToDevice);
    cudaMemcpyAsync(curB, rptrB, N_NODES * sizeof(int), cudaMemcpyDeviceToDevice);
    scatter_kernel<<<GE, 256>>>(row_i, col_i, curF, curB, csrF, csrB);

    prep_wb<<<GP, 256>>>(fg_wih, wbia_f);
    prep_wb<<<GP, 256>>>(bg_wih, wbia_b);

    initT_kernel<<<GT, MTILE>>>(features, init_w, init_b, h);

    float* hc = h;
    float* hn = h2;

    for (int rnd = 0; rnd < 20; rnd++) {
        // forward pass
        mlp_tiled<<<GT, GTB, smem_mlp>>>(hc, fm_w1, fm_b1, fm_w2, fm_b2, m);
        spmm_gather<<<GW, 256>>>(rptrF, csrF, m, msg);
        gi_mma<<<GT, 256, GI_SMEM>>>(msg, wbia_f, fg_bih, gi);
        gate_tiled<<<GT, GTB, smem_gate>>>(gi, hc, fg_whh, fg_bhh, hn);
        { float* t = hc; hc = hn; hn = t; }
        // backward pass
        mlp_tiled<<<GT, GTB, smem_mlp>>>(hc, bm_w1, bm_b1, bm_w2, bm_b2, m);
        spmm_gather<<<GW, 256>>>(rptrB, csrB, m, msg);
        gi_mma<<<GT, 256, GI_SMEM>>>(msg, wbia_b, bg_bih, gi);
        gate_tiled<<<GT, GTB, smem_gate>>>(gi, hc, bg_whh, bg_bhh, hn);
        { float* t = hc; hc = hn; hn = t; }
    }

    classify_kernel<<<GN256, 256>>>(hc, cl_w1, cl_b1, cl_w2, cl_b2, out);
}

// round 14
// speedup vs baseline: 1.0134x; 1.0134x over previous
#include <cuda_runtime.h>
#include <cuda_bf16.h>
#include <cstdint>

#define N_NODES 400000
#define N_EDGES 1600000
#define HDIM 100
#define HDIM3 300
#define ADIM 50
#define CDIM 30
#define GTB 320          // threads for scalar tiled GEMM kernels
#define MTILE 128        // rows per CTA (400000 = 128 * 3125 exactly)
#define SXS 132          // k-major tile row stride

// ---- mma.sync gi GEMM geometry ----
#define BW 17472                 // 56*312 words per B split
#define AW 7680                  // 128*60 words per A split
#define A_OFF (2*BW)             // A base word offset in smem
#define GI_SMEM ((2*BW + 2*AW) * 4)   // 201216 bytes

typedef unsigned long long u64;

// ---------------- scratch (device globals) -------------------------------------
__device__ __align__(16) float g_h  [N_NODES * HDIM];
__device__ __align__(16) float g_h2 [N_NODES * HDIM];
__device__ __align__(16) float g_m  [N_NODES * HDIM];
__device__ __align__(16) float g_msg[N_NODES * HDIM];
__device__ __align__(16) float g_gi [(size_t)N_NODES * HDIM3];
__device__ __align__(16) uint32_t g_wbia[2][2 * BW];   // fwd/bwd wih bf16-split images
__device__ int g_row[N_EDGES];
__device__ int g_col[N_EDGES];
__device__ int g_is64;
__device__ int g_degF[N_NODES];
__device__ int g_degB[N_NODES];
__device__ int g_rptrF[N_NODES + 1];
__device__ int g_rptrB[N_NODES + 1];
__device__ int g_curF[N_NODES];
__device__ int g_curB[N_NODES];
__device__ int g_csrF[N_EDGES];
__device__ int g_csrB[N_EDGES];
__device__ int g_incl[N_NODES];
__device__ int g_bsums[512];

// ---------------- helpers --------------------------------------------------------
__device__ __forceinline__ u64 pack2(float x, float y) {
    u64 r; asm("mov.b64 %0, {%1, %2};" : "=l"(r) : "f"(x), "f"(y)); return r;
}
__device__ __forceinline__ float2 unpack2(u64 v) {
    float2 r; asm("mov.b64 {%0, %1}, %2;" : "=f"(r.x), "=f"(r.y) : "l"(v)); return r;
}
__device__ __forceinline__ void fma2(u64& d, u64 a, u64 b) {
    asm("fma.rn.f32x2 %0, %1, %2, %0;" : "+l"(d) : "l"(a), "l"(b));
}
__device__ __forceinline__ float ex2a(float x) {
    float r; asm("ex2.approx.f32 %0, %1;" : "=f"(r) : "f"(x)); return r;
}
__device__ __forceinline__ float rcpa(float x) {
    float r; asm("rcp.approx.f32 %0, %1;" : "=f"(r) : "f"(x)); return r;
}
__device__ __forceinline__ float fsigmoid(float x) {
    return rcpa(1.0f + ex2a(-1.4426950408889634f * x));
}
__device__ __forceinline__ float ftanh_(float x) {
    float e = ex2a(2.8853900817779268f * x);
    return fmaf(-2.0f, rcpa(e + 1.0f), 1.0f);
}
__device__ __forceinline__ unsigned short bfu(float x) {
    __nv_bfloat16 b = __float2bfloat16(x);
    return *reinterpret_cast<unsigned short*>(&b);
}
__device__ __forceinline__ float bff(float x) {
    return __bfloat162float(__float2bfloat16(x));
}
__device__ __forceinline__ void mma_bf16(float c[4],
    uint32_t a0, uint32_t a1, uint32_t a2, uint32_t a3,
    uint32_t b0, uint32_t b1) {
    asm volatile(
        "mma.sync.aligned.m16n8k16.row.col.f32.bf16.bf16.f32 "
        "{%0,%1,%2,%3}, {%4,%5,%6,%7}, {%8,%9}, {%0,%1,%2,%3};"
        : "+f"(c[0]), "+f"(c[1]), "+f"(c[2]), "+f"(c[3])
        : "r"(a0), "r"(a1), "r"(a2), "r"(a3), "r"(b0), "r"(b1));
}

// ---------------- edge dtype detection & normalization -------------------------
__global__ void detect_kernel(const unsigned int* __restrict__ w) {
    unsigned int v = w[2 * threadIdx.x + 1];
    unsigned int any = __ballot_sync(0xffffffffu, v != 0u);
    if (threadIdx.x == 0) g_is64 = (any == 0u) ? 1 : 0;
}

__global__ void convert_kernel(const void* __restrict__ rp, const void* __restrict__ cp,
                               int* __restrict__ ro, int* __restrict__ co) {
    int e = blockIdx.x * blockDim.x + threadIdx.x;
    if (e >= N_EDGES) return;
    if (g_is64) {
        ro[e] = (int)((const long long*)rp)[e];
        co[e] = (int)((const long long*)cp)[e];
    } else {
        ro[e] = ((const int*)rp)[e];
        co[e] = ((const int*)cp)[e];
    }
}

// ---------------- CSR build ------------------------------------------------------
__global__ void deg_kernel(const int* __restrict__ row, const int* __restrict__ col,
                           int* __restrict__ degF, int* __restrict__ degB) {
    int e = blockIdx.x * blockDim.x + threadIdx.x;
    if (e >= N_EDGES) return;
    atomicAdd(&degF[row[e]], 1);
    atomicAdd(&degB[col[e]], 1);
}

__global__ void scan_block(const int* __restrict__ deg, int* __restrict__ incl,
                           int* __restrict__ bsums, int n) {
    __shared__ int s[1024];
    int i = blockIdx.x * 1024 + threadIdx.x;
    int v = (i < n) ? deg[i] : 0;
    s[threadIdx.x] = v;
    __syncthreads();
    #pragma unroll
    for (int off = 1; off < 1024; off <<= 1) {
        int t = (threadIdx.x >= off) ? s[threadIdx.x - off] : 0;
        __syncthreads();
        s[threadIdx.x] += t;
        __syncthreads();
    }
    if (i < n) incl[i] = s[threadIdx.x];
    if (threadIdx.x == 1023) bsums[blockIdx.x] = s[1023];
}

__global__ void scan_sums(int* __restrict__ bsums, int nb) {
    if (threadIdx.x == 0) {
        int acc = 0;
        for (int b = 0; b < nb; b++) { int t = bsums[b]; bsums[b] = acc; acc += t; }
    }
}

__global__ void scan_final(const int* __restrict__ incl, const int* __restrict__ deg,
                           const int* __restrict__ bsums, int* __restrict__ rptr, int n) {
    int i = blockIdx.x * 256 + threadIdx.x;
    if (i < n) rptr[i] = incl[i] - deg[i] + bsums[i >> 10];
    if (i == n) rptr[n] = N_EDGES;
}

__global__ void scatter_kernel(const int* __restrict__ row, const int* __restrict__ col,
                               int* __restrict__ curF, int* __restrict__ curB,
                               int* __restrict__ csrF, int* __restrict__ csrB) {
    int e = blockIdx.x * blockDim.x + threadIdx.x;
    if (e >= N_EDGES) return;
    int r = row[e], c = col[e];
    int pF = atomicAdd(&curF[r], 1);
    csrF[pF] = c;
    int pB = atomicAdd(&curB[c], 1);
    csrB[pB] = r;
}

// ---------------- weight prep: Wih[100][300] -> 2 bf16-split pair images --------
__global__ void prep_wb(const float* __restrict__ W, uint32_t* __restrict__ o) {
    int e = blockIdx.x * 256 + threadIdx.x;
    if (e >= BW) return;
    int kq = e / 312, n = e - kq * 312;
    int k0 = 2 * kq, k1 = k0 + 1;
    float w0 = (k0 < 100 && n < 300) ? W[k0 * 300 + n] : 0.0f;
    float w1 = (k1 < 100 && n < 300) ? W[k1 * 300 + n] : 0.0f;
    o[e] = (uint32_t)bfu(w0) | ((uint32_t)bfu(w1) << 16);
    float r0 = w0 - bff(w0), r1 = w1 - bff(w1);
    o[BW + e] = (uint32_t)bfu(r0) | ((uint32_t)bfu(r1) << 16);
}

// ---------------- h0_T[d][n] = (features @ init_w + init_b)^T ------------------
__global__ void initT_kernel(const float* __restrict__ f, const float* __restrict__ w,
                             const float* __restrict__ b, float* __restrict__ hT) {
    __shared__ float sw[4 * HDIM];
    __shared__ float sb[HDIM];
    for (int i = threadIdx.x; i < 4 * HDIM; i += blockDim.x) sw[i] = w[i];
    for (int i = threadIdx.x; i < HDIM; i += blockDim.x) sb[i] = b[i];
    __syncthreads();
    int n = blockIdx.x * blockDim.x + threadIdx.x;
    float4 fv = *(const float4*)(f + (size_t)n * 4);
    #pragma unroll 4
    for (int d = 0; d < HDIM; d++) {
        float v = sb[d] + fv.x * sw[d] + fv.y * sw[HDIM + d]
                        + fv.z * sw[2 * HDIM + d] + fv.w * sw[3 * HDIM + d];
        hT[(size_t)d * N_NODES + n] = v;
    }
}

// ---------------- scalar tiled MLP (layer1 packed f32x2) ------------------------
__global__ void __launch_bounds__(GTB, 2) mlp_tiled(
    const float* __restrict__ HT,
    const float* __restrict__ w1, const float* __restrict__ b1,
    const float* __restrict__ w2, const float* __restrict__ b2,
    float* __restrict__ Mout) {
    extern __shared__ float sm[];
    float* sxT = sm;
    float* sw1 = sm + HDIM * SXS;
    float* sw2 = sw1 + 5000;
    float* sb  = sw2 + 5000;
    int base = blockIdx.x * MTILE;
    int lane = threadIdx.x & 31, wid = threadIdx.x >> 5;

    for (int i = threadIdx.x; i < 5000; i += GTB) { sw1[i] = w1[i]; sw2[i] = w2[i]; }
    if (threadIdx.x < 50) sb[threadIdx.x] = b1[threadIdx.x];
    else if (threadIdx.x < 150) sb[threadIdx.x] = b2[threadIdx.x - 50];
    for (int idx = threadIdx.x; idx < HDIM * 32; idx += GTB) {
        int k = idx >> 5, rq = idx & 31;
        *(float4*)(sxT + k * SXS + rq * 4) =
            *(const float4*)(HT + (size_t)k * N_NODES + base + rq * 4);
    }
    __syncthreads();

    u64 a01[5], a23[5];
    #pragma unroll
    for (int j = 0; j < 5; j++) {
        float b = sb[wid * 5 + j];
        u64 bb = pack2(b, b);
        a01[j] = bb; a23[j] = bb;
    }
    const float* xp = sxT + lane * 4;
    for (int k = 0; k < HDIM; k++) {
        float4 a = *(const float4*)(xp + k * SXS);
        u64 axy = pack2(a.x, a.y), azw = pack2(a.z, a.w);
        const float* wr = sw1 + k * ADIM + wid * 5;
        #pragma unroll
        for (int j = 0; j < 5; j++) {
            float wv = wr[j];
            u64 w2 = pack2(wv, wv);
            fma2(a01[j], axy, w2);
            fma2(a23[j], azw, w2);
        }
    }
    __syncthreads();
    #pragma unroll
    for (int j = 0; j < 5; j++) {
        float2 v01 = unpack2(a01[j]);
        float2 v23 = unpack2(a23[j]);
        float* dst = sxT + (wid * 5 + j) * SXS + lane * 4;
        dst[0] = fmaxf(v01.x, 0.0f);
        dst[1] = fmaxf(v01.y, 0.0f);
        dst[2] = fmaxf(v23.x, 0.0f);
        dst[3] = fmaxf(v23.y, 0.0f);
    }
    __syncthreads();

    u64 acc[20];
    const u64* bb = (const u64*)(sb + 50 + wid * 10);
    #pragma unroll
    for (int r = 0; r < 4; r++)
        #pragma unroll
        for (int j = 0; j < 5; j++) acc[r * 5 + j] = bb[j];
    for (int k = 0; k < ADIM; k++) {
        float4 a = *(const float4*)(xp + k * SXS);
        u64 a0 = pack2(a.x, a.x), a1p = pack2(a.y, a.y);
        u64 a2 = pack2(a.z, a.z), a3 = pack2(a.w, a.w);
        const float* wr = sw2 + k * HDIM + wid * 10;
        #pragma unroll
        for (int j = 0; j < 5; j++) {
            u64 wv = *(const u64*)(wr + 2 * j);
            fma2(acc[j],      a0,  wv);
            fma2(acc[5 + j],  a1p, wv);
            fma2(acc[10 + j], a2,  wv);
            fma2(acc[15 + j], a3,  wv);
        }
    }
    __syncthreads();
    #pragma unroll
    for (int j = 0; j < 5; j++) {
        int c = wid * 10 + 2 * j;
        #pragma unroll
        for (int r = 0; r < 4; r++) {
            float2 v = unpack2(acc[r * 5 + j]);
            sxT[c * SXS + lane * 4 + r]       = v.x;
            sxT[(c + 1) * SXS + lane * 4 + r] = v.y;
        }
    }
    __syncthreads();
    for (int idx = threadIdx.x; idx < 25 * MTILE; idx += GTB) {
        int row = idx & 127, c4 = (idx >> 7) * 4;
        float4 v = make_float4(sxT[c4 * SXS + row], sxT[(c4 + 1) * SXS + row],
                               sxT[(c4 + 2) * SXS + row], sxT[(c4 + 3) * SXS + row]);
        *(float4*)(Mout + (size_t)(base + row) * HDIM + c4) = v;
    }
}

// ---------------- warp-per-node CSR gather (index prefetch + 2x unroll) ----------
__global__ void __launch_bounds__(256) spmm_gather(
    const int* __restrict__ rptr, const int* __restrict__ csr,
    const float* __restrict__ m, float* __restrict__ msg) {
    int warp = (blockIdx.x * blockDim.x + threadIdx.x) >> 5;
    int lane = threadIdx.x & 31;
    if (warp >= N_NODES) return;
    int p0 = rptr[warp], p1 = rptr[warp + 1];
    int deg = p1 - p0;
    int pre = (lane < deg) ? csr[p0 + lane] : 0;
    float4 acc0 = make_float4(0.f, 0.f, 0.f, 0.f);
    float4 acc1 = make_float4(0.f, 0.f, 0.f, 0.f);
    int nd = min(deg, 32);
    int j = 0;
    for (; j + 1 < nd; j += 2) {
        int s0 = __shfl_sync(0xffffffffu, pre, j);
        int s1 = __shfl_sync(0xffffffffu, pre, j + 1);
        if (lane < 25) {
            float4 v0 = *(const float4*)(m + (size_t)s0 * HDIM + lane * 4);
            float4 v1 = *(const float4*)(m + (size_t)s1 * HDIM + lane * 4);
            acc0.x += v0.x; acc0.y += v0.y; acc0.z += v0.z; acc0.w += v0.w;
            acc1.x += v1.x; acc1.y += v1.y; acc1.z += v1.z; acc1.w += v1.w;
        }
    }
    if (j < nd) {
        int s0 = __shfl_sync(0xffffffffu, pre, j);
        if (lane < 25) {
            float4 v0 = *(const float4*)(m + (size_t)s0 * HDIM + lane * 4);
            acc0.x += v0.x; acc0.y += v0.y; acc0.z += v0.z; acc0.w += v0.w;
        }
    }
    for (int p = p0 + 32; p < p1; p++) {
        int s = csr[p];
        if (lane < 25) {
            float4 v = *(const float4*)(m + (size_t)s * HDIM + lane * 4);
            acc0.x += v.x; acc0.y += v.y; acc0.z += v.z; acc0.w += v.w;
        }
    }
    if (lane < 25) {
        acc0.x += acc1.x; acc0.y += acc1.y; acc0.z += acc1.z; acc0.w += acc1.w;
        *(float4*)(msg + (size_t)warp * HDIM + lane * 4) = acc0;
    }
}

// ---------------- gi via mma.sync: giT = (msg @ Wih + bih)^T --------------------
template<int NT0, int NT>
__device__ __forceinline__ void gi_compute_half(
    const uint32_t* __restrict__ smu, float* __restrict__ outT,
    const float* __restrict__ Bih, int base, int w, int lane) {
    int q = lane & 3, l4 = lane >> 2;
    int r = w * 16 + l4;
    const uint32_t* A0 = smu + A_OFF + r * 60;
    float c[NT][4];
    #pragma unroll
    for (int t = 0; t < NT; t++) { c[t][0] = c[t][1] = c[t][2] = c[t][3] = 0.0f; }
    #pragma unroll
    for (int ks = 0; ks < 7; ks++) {
        uint32_t a00 = A0[ks * 8 + q],            a01 = A0[480 + ks * 8 + q];
        uint32_t a02 = A0[ks * 8 + 4 + q],        a03 = A0[480 + ks * 8 + 4 + q];
        uint32_t a10 = A0[AW + ks * 8 + q],       a11 = A0[AW + 480 + ks * 8 + q];
        uint32_t a12 = A0[AW + ks * 8 + 4 + q],   a13 = A0[AW + 480 + ks * 8 + 4 + q];
        const uint32_t* B0 = smu + (ks * 8 + q) * 312;
        const uint32_t* B1 = smu + (ks * 8 + 4 + q) * 312;
        #pragma unroll
        for (int t = 0; t < NT; t++) {
            int nb = (NT0 + t) * 8 + l4;
            uint32_t b00 = B0[nb],       b01 = B1[nb];
            uint32_t b10 = B0[BW + nb],  b11 = B1[BW + nb];
            mma_bf16(c[t], a00, a01, a02, a03, b00, b01);
            mma_bf16(c[t], a10, a11, a12, a13, b00, b01);
            mma_bf16(c[t], a00, a01, a02, a03, b10, b11);
        }
    }
    int node = base + r;
    #pragma unroll
    for (int t = 0; t < NT; t++) {
        int n0 = (NT0 + t) * 8 + q * 2;
        if (n0 < 300) {
            float bia = Bih[n0];
            outT[(size_t)n0 * N_NODES + node]     = c[t][0] + bia;
            outT[(size_t)n0 * N_NODES + node + 8] = c[t][2] + bia;
        }
        if (n0 + 1 < 300) {
            float bib = Bih[n0 + 1];
            outT[(size_t)(n0 + 1) * N_NODES + node]     = c[t][1] + bib;
            outT[(size_t)(n0 + 1) * N_NODES + node + 8] = c[t][3] + bib;
        }
    }
}

__global__ void __launch_bounds__(256, 1) gi_mma(
    const float* __restrict__ MSG, const uint32_t* __restrict__ GB,
    const float* __restrict__ Bih, float* __restrict__ outT) {
    extern __shared__ __align__(16) uint32_t smu[];
    int tid = threadIdx.x;
    int base = blockIdx.x * MTILE;
    {
        const uint4* src = (const uint4*)GB;
        uint4* dst = (uint4*)smu;
        for (int i = tid; i < (2 * BW) / 4; i += 256) dst[i] = src[i];
    }
    for (int idx = tid; idx < 128 * 56; idx += 256) {
        int row = idx / 56;
        int kq = idx - row * 56;
        float2 v = make_float2(0.0f, 0.0f);
        if (kq < 50) v = *(const float2*)(MSG + (size_t)(base + row) * HDIM + 2 * kq);
        uint32_t hi = (uint32_t)bfu(v.x) | ((uint32_t)bfu(v.y) << 16);
        float rx = v.x - bff(v.x), ry = v.y - bff(v.y);
        uint32_t lo = (uint32_t)bfu(rx) | ((uint32_t)bfu(ry) << 16);
        smu[A_OFF + row * 60 + kq]      = hi;
        smu[A_OFF + AW + row * 60 + kq] = lo;
    }
    __syncthreads();
    int w = tid >> 5, lane = tid & 31;
    gi_compute_half<0, 19>(smu, outT, Bih, base, w, lane);
    gi_compute_half<19, 20>(smu, outT, Bih, base, w, lane);
}

// ---------------- tiled gate: R12 blocking + gate-interleaved W (2 LDS per k) ---
__global__ void __launch_bounds__(GTB, 2) gate_tiled(
    const float* __restrict__ GIT,
    const float* __restrict__ HT,
    const float* __restrict__ W, const float* __restrict__ B,
    float* __restrict__ HoutT) {
    extern __shared__ float sm[];
    float* sxT = sm;                  // 100 x 132
    float* sw  = sm + HDIM * SXS;     // 100 x 80 (interleaved: [k][wid*8 + g*2 + j])
    float* sb  = sw + 8000;           // 300
    int base = blockIdx.x * MTILE;
    int lane = threadIdx.x & 31, wid = threadIdx.x >> 5;
    for (int i = threadIdx.x; i < HDIM3; i += GTB) sb[i] = B[i];
    for (int idx = threadIdx.x; idx < HDIM * 32; idx += GTB) {
        int k = idx >> 5, rq = idx & 31;
        *(float4*)(sxT + k * SXS + rq * 4) =
            *(const float4*)(HT + (size_t)k * N_NODES + base + rq * 4);
    }
    const float* xp = sxT + lane * 4;
    size_t rowoff = base + lane * 4;
    for (int ch = 0; ch < 5; ch++) {
        int d0 = ch * 20;
        __syncthreads();
        // stage interleaved: sw[k*80 + wd*8 + g*2 + j] = W[k*300 + g*100 + d0 + wd*2 + j]
        for (int i = threadIdx.x; i < 3000; i += GTB) {
            int k = i / 30, rem = i - k * 30;
            int wd = rem / 3, g = rem - wd * 3;
            float2 v = *(const float2*)(W + (size_t)k * HDIM3 + g * HDIM + d0 + wd * 2);
            *(float2*)(sw + k * 80 + wd * 8 + g * 2) = v;
        }
        __syncthreads();
        int cl = wid * 2;
        u64 ar[4], az[4], an[4];
        {
            u64 br = *(const u64*)(sb + d0 + cl);
            u64 bz = *(const u64*)(sb + HDIM + d0 + cl);
            u64 bn = *(const u64*)(sb + 2 * HDIM + d0 + cl);
            #pragma unroll
            for (int r = 0; r < 4; r++) { ar[r] = br; az[r] = bz; an[r] = bn; }
        }
        for (int k = 0; k < HDIM; k++) {
            float4 a = *(const float4*)(xp + k * SXS);
            u64 a0 = pack2(a.x, a.x), a1p = pack2(a.y, a.y);
            u64 a2 = pack2(a.z, a.z), a3 = pack2(a.w, a.w);
            const u64* wk = (const u64*)(sw + k * 80 + wid * 8);   // 16B aligned
            ulonglong2 wrz = *(const ulonglong2*)wk;               // LDS.128: wr|wz
            u64 wnv = wk[2];                                       // LDS.64 : wn
            fma2(ar[0], a0, wrz.x); fma2(ar[1], a1p, wrz.x);
            fma2(ar[2], a2, wrz.x); fma2(ar[3], a3, wrz.x);
            fma2(az[0], a0, wrz.y); fma2(az[1], a1p, wrz.y);
            fma2(az[2], a2, wrz.y); fma2(az[3], a3, wrz.y);
            fma2(an[0], a0, wnv); fma2(an[1], a1p, wnv);
            fma2(an[2], a2, wnv); fma2(an[3], a3, wnv);
        }
        int c = d0 + cl;
        float4 gr0 = *(const float4*)(GIT + (size_t)c * N_NODES + rowoff);
        float4 gr1 = *(const float4*)(GIT + (size_t)(c + 1) * N_NODES + rowoff);
        float4 gz0 = *(const float4*)(GIT + (size_t)(HDIM + c) * N_NODES + rowoff);
        float4 gz1 = *(const float4*)(GIT + (size_t)(HDIM + c + 1) * N_NODES + rowoff);
        float4 gn0 = *(const float4*)(GIT + (size_t)(2 * HDIM + c) * N_NODES + rowoff);
        float4 gn1 = *(const float4*)(GIT + (size_t)(2 * HDIM + c + 1) * N_NODES + rowoff);
        float4 h0 = *(const float4*)(sxT + c * SXS + lane * 4);
        float4 h1 = *(const float4*)(sxT + (c + 1) * SXS + lane * 4);
        float4 o0, o1;
        {
            const float* grp0 = &gr0.x; const float* grp1 = &gr1.x;
            const float* gzp0 = &gz0.x; const float* gzp1 = &gz1.x;
            const float* gnp0 = &gn0.x; const float* gnp1 = &gn1.x;
            const float* hp0 = &h0.x;  const float* hp1 = &h1.x;
            float* op0 = &o0.x; float* op1 = &o1.x;
            #pragma unroll
            for (int r = 0; r < 4; r++) {
                float2 hr = unpack2(ar[r]);
                float2 hz = unpack2(az[r]);
                float2 hn = unpack2(an[r]);
                float r0 = fsigmoid(grp0[r] + hr.x);
                float r1 = fsigmoid(grp1[r] + hr.y);
                float z0 = fsigmoid(gzp0[r] + hz.x);
                float z1 = fsigmoid(gzp1[r] + hz.y);
                float n0 = ftanh_(gnp0[r] + r0 * hn.x);
                float n1 = ftanh_(gnp1[r] + r1 * hn.y);
                op0[r] = (1.0f - z0) * n0 + z0 * hp0[r];
                op1[r] = (1.0f - z1) * n1 + z1 * hp1[r];
            }
        }
        *(float4*)(HoutT + (size_t)c * N_NODES + rowoff) = o0;
        *(float4*)(HoutT + (size_t)(c + 1) * N_NODES + rowoff) = o1;
    }
}

// ---------------- classifier from transposed h ----------------------------------
__global__ void __launch_bounds__(256) classify_kernel(
    const float* __restrict__ HT,
    const float* __restrict__ w1, const float* __restrict__ b1,
    const float* __restrict__ w2, const float* __restrict__ b2,
    float* __restrict__ out) {
    __shared__ float s1[HDIM * CDIM];
    __shared__ float sb1[CDIM];
    __shared__ float s2[CDIM];
    __shared__ float sb2;
    for (int i = threadIdx.x; i < HDIM * CDIM; i += blockDim.x) s1[i] = w1[i];
    for (int i = threadIdx.x; i < CDIM; i += blockDim.x) { sb1[i] = b1[i]; s2[i] = w2[i]; }
    if (threadIdx.x == 0) sb2 = b2[0];
    __syncthreads();
    int n = blockIdx.x * blockDim.x + threadIdx.x;
    if (n >= N_NODES) return;
    float a[CDIM];
    #pragma unroll
    for (int j = 0; j < CDIM; j++) a[j] = sb1[j];
    for (int k = 0; k < HDIM; k++) {
        float xv = HT[(size_t)k * N_NODES + n];
        const float* wr = s1 + k * CDIM;
        #pragma unroll
        for (int j = 0; j < CDIM; j++) a[j] = fmaf(xv, wr[j], a[j]);
    }
    float r = sb2;
    #pragma unroll
    for (int j = 0; j < CDIM; j++) r = fmaf(fmaxf(a[j], 0.0f), s2[j], r);
    out[n] = r;
}

// ---------------- host orchestration --------------------------------------------
extern "C" void kernel_launch(void* const* d_in, const int* in_sizes, int n_in,
                              void* d_out, int out_size) {
    const float* features = (const float*)d_in[0];
    const void*  e_row    = d_in[1];
    const void*  e_col    = d_in[2];
    const float* init_w   = (const float*)d_in[3];
    const float* init_b   = (const float*)d_in[4];
    const float* fm_w1 = (const float*)d_in[5],  *fm_b1 = (const float*)d_in[6];
    const float* fm_w2 = (const float*)d_in[7],  *fm_b2 = (const float*)d_in[8];
    const float* bm_w1 = (const float*)d_in[9],  *bm_b1 = (const float*)d_in[10];
    const float* bm_w2 = (const float*)d_in[11], *bm_b2 = (const float*)d_in[12];
    const float* fg_wih = (const float*)d_in[13], *fg_whh = (const float*)d_in[14];
    const float* fg_bih = (const float*)d_in[15], *fg_bhh = (const float*)d_in[16];
    const float* bg_wih = (const float*)d_in[17], *bg_whh = (const float*)d_in[18];
    const float* bg_bih = (const float*)d_in[19], *bg_bhh = (const float*)d_in[20];
    const float* cl_w1 = (const float*)d_in[21], *cl_b1 = (const float*)d_in[22];
    const float* cl_w2 = (const float*)d_in[23], *cl_b2 = (const float*)d_in[24];
    float* out = (float*)d_out;

    float *h, *h2, *m, *msg, *gi;
    int *row_i, *col_i, *degF, *degB, *rptrF, *rptrB, *curF, *curB, *csrF, *csrB, *incl, *bsums;
    uint32_t* wbia;
    cudaGetSymbolAddress((void**)&h,     g_h);
    cudaGetSymbolAddress((void**)&h2,    g_h2);
    cudaGetSymbolAddress((void**)&m,     g_m);
    cudaGetSymbolAddress((void**)&msg,   g_msg);
    cudaGetSymbolAddress((void**)&gi,    g_gi);
    cudaGetSymbolAddress((void**)&wbia,  g_wbia);
    cudaGetSymbolAddress((void**)&row_i, g_row);
    cudaGetSymbolAddress((void**)&col_i, g_col);
    cudaGetSymbolAddress((void**)&degF,  g_degF);
    cudaGetSymbolAddress((void**)&degB,  g_degB);
    cudaGetSymbolAddress((void**)&rptrF, g_rptrF);
    cudaGetSymbolAddress((void**)&rptrB, g_rptrB);
    cudaGetSymbolAddress((void**)&curF,  g_curF);
    cudaGetSymbolAddress((void**)&curB,  g_curB);
    cudaGetSymbolAddress((void**)&csrF,  g_csrF);
    cudaGetSymbolAddress((void**)&csrB,  g_csrB);
    cudaGetSymbolAddress((void**)&incl,  g_incl);
    cudaGetSymbolAddress((void**)&bsums, g_bsums);

    uint32_t* wbia_f = wbia;
    uint32_t* wbia_b = wbia + 2 * BW;

    const size_t smem_mlp  = (size_t)(HDIM * SXS + 5000 + 5000 + 150) * sizeof(float);
    const size_t smem_gate = (size_t)(HDIM * SXS + 8000 + 300) * sizeof(float);   // 86,000
    cudaFuncSetAttribute(mlp_tiled,  cudaFuncAttributeMaxDynamicSharedMemorySize, (int)smem_mlp);
    cudaFuncSetAttribute(gate_tiled, cudaFuncAttributeMaxDynamicSharedMemorySize, (int)smem_gate);
    cudaFuncSetAttribute(gi_mma,     cudaFuncAttributeMaxDynamicSharedMemorySize, GI_SMEM);

    const int GT    = N_NODES / MTILE;   // 3125
    const int GN256 = (N_NODES + 255) / 256;
    const int GE    = (N_EDGES + 255) / 256;
    const int GW    = (int)(((long long)N_NODES * 32 + 255) / 256);
    const int NB    = (N_NODES + 1023) / 1024;
    const int GP    = (BW + 255) / 256;

    // ---- preprocessing ----
    detect_kernel<<<1, 32>>>((const unsigned int*)e_row);
    convert_kernel<<<GE, 256>>>(e_row, e_col, row_i, col_i);
    cudaMemsetAsync(degF, 0, N_NODES * sizeof(int));
    cudaMemsetAsync(degB, 0, N_NODES * sizeof(int));
    deg_kernel<<<GE, 256>>>(row_i, col_i, degF, degB);
    scan_block<<<NB, 1024>>>(degF, incl, bsums, N_NODES);
    scan_sums<<<1, 32>>>(bsums, NB);
    scan_final<<<(N_NODES + 256) / 256, 256>>>(incl, degF, bsums, rptrF, N_NODES);
    scan_block<<<NB, 1024>>>(degB, incl, bsums, N_NODES);
    scan_sums<<<1, 32>>>(bsums, NB);
    scan_final<<<(N_NODES + 256) / 256, 256>>>(incl, degB, bsums, rptrB, N_NODES);
    cudaMemcpyAsync(curF, rptrF, N_NODES * sizeof(int), cudaMemcpyDeviceToDevice);
    cudaMemcpyAsync(curB, rptrB, N_NODES * sizeof(int), cudaMemcpyDeviceToDevice);
    scatter_kernel<<<GE, 256>>>(row_i, col_i, curF, curB, csrF, csrB);

    prep_wb<<<GP, 256>>>(fg_wih, wbia_f);
    prep_wb<<<GP, 256>>>(bg_wih, wbia_b);

    initT_kernel<<<GT, MTILE>>>(features, init_w, init_b, h);

    float* hc = h;
    float* hn = h2;

    for (int rnd = 0; rnd < 20; rnd++) {
        // forward pass
        mlp_tiled<<<GT, GTB, smem_mlp>>>(hc, fm_w1, fm_b1, fm_w2, fm_b2, m);
        spmm_gather<<<GW, 256>>>(rptrF, csrF, m, msg);
        gi_mma<<<GT, 256, GI_SMEM>>>(msg, wbia_f, fg_bih, gi);
        gate_tiled<<<GT, GTB, smem_gate>>>(gi, hc, fg_whh, fg_bhh, hn);
        { float* t = hc; hc = hn; hn = t; }
        // backward pass
        mlp_tiled<<<GT, GTB, smem_mlp>>>(hc, bm_w1, bm_b1, bm_w2, bm_b2, m);
        spmm_gather<<<GW, 256>>>(rptrB, csrB, m, msg);
        gi_mma<<<GT, 256, GI_SMEM>>>(msg, wbia_b, bg_bih, gi);
        gate_tiled<<<GT, GTB, smem_gate>>>(gi, hc, bg_whh, bg_bhh, hn);
        { float* t = hc; hc = hn; hn = t; }
    }

    classify_kernel<<<GN256, 256>>>(hc, cl_w1, cl_b1, cl_w2, cl_b2, out);
}